// round 4
// baseline (speedup 1.0000x reference)
#include <cuda_runtime.h>
#include <cuda_bf16.h>
#include <cstdint>
#include <math.h>

#define Bq 4
#define Sq 2048
#define DMq 512
#define Hq 8
#define BSq (Bq * Sq)
#define Y_ELEMS ((size_t)Bq * Sq * DMq)
#define NROWS (Bq * Hq * Sq)          // 65536 attention rows
#define NTILES 16                     // 2048 / 128 k-tiles

// Scratch (__device__ globals; no allocation allowed)
__device__ __nv_bfloat16 g_qhi[Bq * Sq * DMq];
__device__ __nv_bfloat16 g_qlo[Bq * Sq * DMq];
__device__ __nv_bfloat16 g_khi[Bq * Sq * DMq];
__device__ __nv_bfloat16 g_klo[Bq * Sq * DMq];
__device__ __nv_bfloat16 g_vhi[Bq * Sq * DMq];
__device__ __nv_bfloat16 g_vlo[Bq * Sq * DMq];
__device__ float g_ctx[Bq * Sq * DMq];
__device__ float g_pm[(size_t)NROWS * NTILES];   // partial row max per k-tile
__device__ float g_pz[(size_t)NROWS * NTILES];   // partial row expsum per k-tile
__device__ float g_rowm[NROWS];                  // final row max
__device__ float g_rowinv[NROWS];                // final 1/Z

// ---------------------------------------------------------------------------
__device__ __forceinline__ uint32_t smem_u32(const void* p) {
    uint32_t a;
    asm("{ .reg .u64 t; cvta.to.shared.u64 t, %1; cvt.u32.u64 %0, t; }"
        : "=r"(a) : "l"(p));
    return a;
}

__device__ __forceinline__ void ldsm_x4(uint32_t* r, uint32_t addr) {
    asm volatile("ldmatrix.sync.aligned.m8n8.x4.shared.b16 {%0,%1,%2,%3}, [%4];"
                 : "=r"(r[0]), "=r"(r[1]), "=r"(r[2]), "=r"(r[3]) : "r"(addr));
}

__device__ __forceinline__ void ldsm_x4_trans(uint32_t* r, uint32_t addr) {
    asm volatile("ldmatrix.sync.aligned.m8n8.x4.trans.shared.b16 {%0,%1,%2,%3}, [%4];"
                 : "=r"(r[0]), "=r"(r[1]), "=r"(r[2]), "=r"(r[3]) : "r"(addr));
}

__device__ __forceinline__ void mma_bf16(float* d, const uint32_t* a,
                                         uint32_t b0, uint32_t b1) {
    asm volatile(
        "mma.sync.aligned.m16n8k16.row.col.f32.bf16.bf16.f32 "
        "{%0,%1,%2,%3}, {%4,%5,%6,%7}, {%8,%9}, {%0,%1,%2,%3};"
        : "+f"(d[0]), "+f"(d[1]), "+f"(d[2]), "+f"(d[3])
        : "r"(a[0]), "r"(a[1]), "r"(a[2]), "r"(a[3]), "r"(b0), "r"(b1));
}

__device__ __forceinline__ uint32_t pack_bf16(float x, float y) {
    __nv_bfloat162 t = __floats2bfloat162_rn(x, y);
    return *reinterpret_cast<uint32_t*>(&t);
}

// ---------------------------------------------------------------------------
// Projection GEMM + bias, 128x128 tile, BK=16, 256 threads, 8x8/thread.
// ---------------------------------------------------------------------------
__global__ __launch_bounds__(256) void gemm_bias128_kernel(
    const float* __restrict__ A, const float* __restrict__ W,
    const float* __restrict__ bias, float* __restrict__ Cf,
    __nv_bfloat16* __restrict__ Chi, __nv_bfloat16* __restrict__ Clo,
    int M, int N, int K)
{
    __shared__ float As[16][132];
    __shared__ float Ws[16][132];
    int tid = threadIdx.x;
    int ty = tid >> 4, tx = tid & 15;
    int m0 = blockIdx.y * 128, n0 = blockIdx.x * 128;

    float acc[8][8] = {};
    int lrow = tid >> 1;
    int lseg = (tid & 1) * 8;
    int wrow = tid >> 4;
    int wcol = (tid & 15) * 8;

    for (int k0 = 0; k0 < K; k0 += 16) {
        float4 a0 = *(const float4*)&A[(size_t)(m0 + lrow) * K + k0 + lseg];
        float4 a1 = *(const float4*)&A[(size_t)(m0 + lrow) * K + k0 + lseg + 4];
        As[lseg + 0][lrow] = a0.x; As[lseg + 1][lrow] = a0.y;
        As[lseg + 2][lrow] = a0.z; As[lseg + 3][lrow] = a0.w;
        As[lseg + 4][lrow] = a1.x; As[lseg + 5][lrow] = a1.y;
        As[lseg + 6][lrow] = a1.z; As[lseg + 7][lrow] = a1.w;
        float4 w0 = *(const float4*)&W[(size_t)(k0 + wrow) * N + n0 + wcol];
        float4 w1 = *(const float4*)&W[(size_t)(k0 + wrow) * N + n0 + wcol + 4];
        *(float4*)&Ws[wrow][wcol] = w0;
        *(float4*)&Ws[wrow][wcol + 4] = w1;
        __syncthreads();
#pragma unroll
        for (int kk = 0; kk < 16; kk++) {
            float4 af0 = *(float4*)&As[kk][ty * 8];
            float4 af1 = *(float4*)&As[kk][ty * 8 + 4];
            float4 bf0 = *(float4*)&Ws[kk][tx * 8];
            float4 bf1 = *(float4*)&Ws[kk][tx * 8 + 4];
            float a[8] = {af0.x, af0.y, af0.z, af0.w, af1.x, af1.y, af1.z, af1.w};
            float bb[8] = {bf0.x, bf0.y, bf0.z, bf0.w, bf1.x, bf1.y, bf1.z, bf1.w};
#pragma unroll
            for (int i = 0; i < 8; i++)
#pragma unroll
                for (int j = 0; j < 8; j++)
                    acc[i][j] = fmaf(a[i], bb[j], acc[i][j]);
        }
        __syncthreads();
    }

    float bv[8];
#pragma unroll
    for (int j = 0; j < 8; j++) bv[j] = bias[n0 + tx * 8 + j];

#pragma unroll
    for (int i = 0; i < 8; i++) {
        size_t row = (size_t)(m0 + ty * 8 + i);
#pragma unroll
        for (int j = 0; j < 8; j++) {
            size_t idx = row * N + n0 + tx * 8 + j;
            float val = acc[i][j] + bv[j];
            if (Cf) Cf[idx] = val;
            if (Chi) {
                __nv_bfloat16 hb = __float2bfloat16_rn(val);
                float rem = val - __bfloat162float(hb);
                Chi[idx] = hb;
                Clo[idx] = __float2bfloat16_rn(rem);
            }
        }
    }
}

// ---------------------------------------------------------------------------
// scores via mma.sync bf16x3, writes raw masked scores + per-tile softmax
// partials (row max, row expsum).
// ---------------------------------------------------------------------------
#define SC_TILE_BYTES (128 * 144)
#define SC_STATS_OFF (4 * SC_TILE_BYTES)
#define SC_SMEM_BYTES (4 * SC_TILE_BYTES + 2048)

__global__ __launch_bounds__(256, 2) void scores_mma_kernel(
    const __nv_bfloat16* __restrict__ qhi, const __nv_bfloat16* __restrict__ qlo,
    const __nv_bfloat16* __restrict__ khi, const __nv_bfloat16* __restrict__ klo,
    const float* __restrict__ mask, float* __restrict__ att,
    float* __restrict__ pm, float* __restrict__ pz)
{
    extern __shared__ char sm[];
    char* bp = sm;
    uint32_t sb = smem_u32(sm);
    const uint32_t QHIo = 0, QLOo = SC_TILE_BYTES, KHIo = 2 * SC_TILE_BYTES,
                   KLOo = 3 * SC_TILE_BYTES;
    float* sm_m = (float*)(bp + SC_STATS_OFF);      // [2][128]
    float* sm_z = sm_m + 256;                        // [2][128]

    int tid = threadIdx.x;
    int lane = tid & 31, wid = tid >> 5;
    int wq = wid >> 1, wn = wid & 1;
    int bh = blockIdx.z, b = bh >> 3, h = bh & 7;
    int q0 = blockIdx.y * 128;
    int n0 = blockIdx.x * 128;

    for (int it = tid; it < 1024; it += 256) {
        int row = it >> 3, ch = it & 7;
        int so = row * 144 + ch * 16;
        size_t gq = ((size_t)(b * Sq + q0 + row)) * DMq + h * 64 + ch * 8;
        size_t gk = ((size_t)(b * Sq + n0 + row)) * DMq + h * 64 + ch * 8;
        *(uint4*)(bp + QHIo + so) = *(const uint4*)(qhi + gq);
        *(uint4*)(bp + QLOo + so) = *(const uint4*)(qlo + gq);
        *(uint4*)(bp + KHIo + so) = *(const uint4*)(khi + gk);
        *(uint4*)(bp + KLOo + so) = *(const uint4*)(klo + gk);
    }
    __syncthreads();

    float acc[2][8][4] = {};

    const uint32_t Aoff[3] = {QHIo, QHIo, QLOo};
    const uint32_t Boff[3] = {KHIo, KLOo, KHIo};

#pragma unroll
    for (int p = 0; p < 3; p++) {
        uint32_t abase = sb + Aoff[p] + (wq * 32) * 144;
        uint32_t bbase = sb + Boff[p] + (wn * 64) * 144;
        uint32_t arow = lane & 15;
        uint32_t acolb = (lane >> 4) * 16;
#pragma unroll
        for (int kt = 0; kt < 4; kt++) {
            uint32_t a0[4], a1[4];
            ldsm_x4(a0, abase + arow * 144 + acolb + kt * 32);
            ldsm_x4(a1, abase + (16 + arow) * 144 + acolb + kt * 32);
            uint32_t brow = (lane & 7) + ((lane & 16) ? 8 : 0);
            uint32_t bcolb = ((lane >> 3) & 1) * 16 + kt * 32;
#pragma unroll
            for (int np = 0; np < 4; np++) {
                uint32_t bb[4];
                ldsm_x4(bb, bbase + (brow + np * 16) * 144 + bcolb);
                mma_bf16(acc[0][np * 2 + 0], a0, bb[0], bb[1]);
                mma_bf16(acc[0][np * 2 + 1], a0, bb[2], bb[3]);
                mma_bf16(acc[1][np * 2 + 0], a1, bb[0], bb[1]);
                mma_bf16(acc[1][np * 2 + 1], a1, bb[2], bb[3]);
            }
        }
    }

    // Epilogue pass 1: scale + mask, store raw scores, track per-row max.
    int g = lane >> 2, tg = lane & 3;
    float mrow[4] = {-1e30f, -1e30f, -1e30f, -1e30f};   // [mi*2 + half]
#pragma unroll
    for (int ni = 0; ni < 8; ni++) {
        int col = n0 + wn * 64 + ni * 8 + tg * 2;
        float2 mv = *(const float2*)&mask[(size_t)b * Sq + col];
        float mx = mv.x * -1e9f, my = mv.y * -1e9f;
#pragma unroll
        for (int mi = 0; mi < 2; mi++) {
            int row = q0 + wq * 32 + mi * 16 + g;
            float v0 = acc[mi][ni][0] * 0.125f + mx;
            float v1 = acc[mi][ni][1] * 0.125f + my;
            float v2 = acc[mi][ni][2] * 0.125f + mx;
            float v3 = acc[mi][ni][3] * 0.125f + my;
            mrow[mi * 2 + 0] = fmaxf(mrow[mi * 2 + 0], fmaxf(v0, v1));
            mrow[mi * 2 + 1] = fmaxf(mrow[mi * 2 + 1], fmaxf(v2, v3));
            *(float2*)&att[((size_t)bh * Sq + row) * Sq + col] = make_float2(v0, v1);
            *(float2*)&att[((size_t)bh * Sq + row + 8) * Sq + col] = make_float2(v2, v3);
        }
    }
    // Reduce max across the 4 tg lanes sharing a row
#pragma unroll
    for (int r = 0; r < 4; r++) {
        mrow[r] = fmaxf(mrow[r], __shfl_xor_sync(0xffffffffu, mrow[r], 1));
        mrow[r] = fmaxf(mrow[r], __shfl_xor_sync(0xffffffffu, mrow[r], 2));
    }
    // Pass 2: expsum against warp-local row max
    float zrow[4] = {0.f, 0.f, 0.f, 0.f};
#pragma unroll
    for (int ni = 0; ni < 8; ni++) {
        int col = n0 + wn * 64 + ni * 8 + tg * 2;
        float2 mv = *(const float2*)&mask[(size_t)b * Sq + col];
        float mx = mv.x * -1e9f, my = mv.y * -1e9f;
#pragma unroll
        for (int mi = 0; mi < 2; mi++) {
            float v0 = acc[mi][ni][0] * 0.125f + mx;
            float v1 = acc[mi][ni][1] * 0.125f + my;
            float v2 = acc[mi][ni][2] * 0.125f + mx;
            float v3 = acc[mi][ni][3] * 0.125f + my;
            zrow[mi * 2 + 0] += __expf(v0 - mrow[mi * 2 + 0]) + __expf(v1 - mrow[mi * 2 + 0]);
            zrow[mi * 2 + 1] += __expf(v2 - mrow[mi * 2 + 1]) + __expf(v3 - mrow[mi * 2 + 1]);
        }
    }
#pragma unroll
    for (int r = 0; r < 4; r++) {
        zrow[r] += __shfl_xor_sync(0xffffffffu, zrow[r], 1);
        zrow[r] += __shfl_xor_sync(0xffffffffu, zrow[r], 2);
    }
    if (tg == 0) {
#pragma unroll
        for (int mi = 0; mi < 2; mi++) {
#pragma unroll
            for (int half = 0; half < 2; half++) {
                int rloc = wq * 32 + mi * 16 + g + half * 8;
                sm_m[wn * 128 + rloc] = mrow[mi * 2 + half];
                sm_z[wn * 128 + rloc] = zrow[mi * 2 + half];
            }
        }
    }
    __syncthreads();
    if (tid < 128) {
        float m0 = sm_m[tid], m1 = sm_m[128 + tid];
        float mm = fmaxf(m0, m1);
        float zz = sm_z[tid] * __expf(m0 - mm) + sm_z[128 + tid] * __expf(m1 - mm);
        size_t pidx = ((size_t)bh * Sq + q0 + tid) * NTILES + blockIdx.x;
        pm[pidx] = mm;
        pz[pidx] = zz;
    }
}

// ---------------------------------------------------------------------------
// Combine per-tile partials into per-row (max, 1/Z)
// ---------------------------------------------------------------------------
__global__ __launch_bounds__(256) void softmax_reduce_kernel(
    const float* __restrict__ pm, const float* __restrict__ pz,
    float* __restrict__ rowm, float* __restrict__ rowinv)
{
    int idx = blockIdx.x * 256 + threadIdx.x;
    if (idx >= NROWS) return;
    const float* pmp = pm + (size_t)idx * NTILES;
    const float* pzp = pz + (size_t)idx * NTILES;
    float m = -1e30f;
#pragma unroll
    for (int t = 0; t < NTILES; t++) m = fmaxf(m, pmp[t]);
    float z = 0.f;
#pragma unroll
    for (int t = 0; t < NTILES; t++) z += pzp[t] * __expf(pmp[t] - m);
    rowm[idx] = m;
    rowinv[idx] = 1.0f / z;
}

// ---------------------------------------------------------------------------
// ctx = softmax(att_raw) @ V via mma.sync bf16x3; also writes normalized att.
// ---------------------------------------------------------------------------
#define CTX_A_BYTES (128 * 144)
#define CTX_V_BYTES (64 * 144)
#define CTX_SMEM_BYTES (2 * CTX_A_BYTES + 2 * CTX_V_BYTES + 1024)

__global__ __launch_bounds__(256) void ctx_mma_kernel(
    float* __restrict__ att,
    const __nv_bfloat16* __restrict__ vhi, const __nv_bfloat16* __restrict__ vlo,
    const float* __restrict__ rowm, const float* __restrict__ rowinv,
    float* __restrict__ ctx)
{
    extern __shared__ char sm[];
    char* bp = sm;
    uint32_t sb = smem_u32(sm);
    const uint32_t AHIo = 0, ALOo = CTX_A_BYTES,
                   VHIo = 2 * CTX_A_BYTES, VLOo = 2 * CTX_A_BYTES + CTX_V_BYTES;
    float* sm_m = (float*)(bp + 2 * CTX_A_BYTES + 2 * CTX_V_BYTES);  // [128]
    float* sm_iz = sm_m + 128;                                        // [128]

    int tid = threadIdx.x;
    int lane = tid & 31, wid = tid >> 5;
    int bh = blockIdx.y, b = bh >> 3, h = bh & 7;
    int q0 = blockIdx.x * 128;

    if (tid < 128) {
        sm_m[tid] = rowm[(size_t)bh * Sq + q0 + tid];
        sm_iz[tid] = rowinv[(size_t)bh * Sq + q0 + tid];
    }
    __syncthreads();

    float acc[8][4] = {};

    for (int k0 = 0; k0 < Sq; k0 += 64) {
        for (int it = tid; it < 2048; it += 256) {
            int row = it >> 4, c4 = (it & 15) * 4;
            float* ap = &att[((size_t)bh * Sq + q0 + row) * Sq + k0 + c4];
            float4 t = *(const float4*)ap;
            float mr = sm_m[row], iz = sm_iz[row];
            t.x = __expf(t.x - mr) * iz;
            t.y = __expf(t.y - mr) * iz;
            t.z = __expf(t.z - mr) * iz;
            t.w = __expf(t.w - mr) * iz;
            *(float4*)ap = t;   // normalized att out
            __nv_bfloat16 h0 = __float2bfloat16_rn(t.x);
            __nv_bfloat16 h1 = __float2bfloat16_rn(t.y);
            __nv_bfloat16 h2 = __float2bfloat16_rn(t.z);
            __nv_bfloat16 h3 = __float2bfloat16_rn(t.w);
            uint2 hp, lp;
            hp.x = pack_bf16(__bfloat162float(h0), __bfloat162float(h1));
            hp.y = pack_bf16(__bfloat162float(h2), __bfloat162float(h3));
            lp.x = pack_bf16(t.x - __bfloat162float(h0), t.y - __bfloat162float(h1));
            lp.y = pack_bf16(t.z - __bfloat162float(h2), t.w - __bfloat162float(h3));
            int so = row * 144 + c4 * 2;
            *(uint2*)(bp + AHIo + so) = hp;
            *(uint2*)(bp + ALOo + so) = lp;
        }
        for (int it = tid; it < 512; it += 256) {
            int row = it >> 3, ch = it & 7;
            int so = row * 144 + ch * 16;
            size_t gv = ((size_t)(b * Sq + k0 + row)) * DMq + h * 64 + ch * 8;
            *(uint4*)(bp + VHIo + so) = *(const uint4*)(vhi + gv);
            *(uint4*)(bp + VLOo + so) = *(const uint4*)(vlo + gv);
        }
        __syncthreads();

        const uint32_t Aoff[3] = {AHIo, ALOo, AHIo};
        const uint32_t Boff[3] = {VHIo, VHIo, VLOo};
#pragma unroll
        for (int p = 0; p < 3; p++) {
            uint32_t abase = sb + Aoff[p] + (wid * 16) * 144;
            uint32_t bbase = sb + Boff[p];
            uint32_t arow = lane & 15;
            uint32_t acolb = (lane >> 4) * 16;
            uint32_t brow = (lane & 7) + ((lane & 8) ? 8 : 0);
            uint32_t bcolb = (lane & 16) ? 16 : 0;
#pragma unroll
            for (int kt = 0; kt < 4; kt++) {
                uint32_t a0[4];
                ldsm_x4(a0, abase + arow * 144 + acolb + kt * 32);
#pragma unroll
                for (int np = 0; np < 4; np++) {
                    uint32_t bb[4];
                    ldsm_x4_trans(bb, bbase + (kt * 16 + brow) * 144 + np * 32 + bcolb);
                    mma_bf16(acc[np * 2 + 0], a0, bb[0], bb[1]);
                    mma_bf16(acc[np * 2 + 1], a0, bb[2], bb[3]);
                }
            }
        }
        __syncthreads();
    }

    int g = lane >> 2, tg = lane & 3;
#pragma unroll
    for (int ni = 0; ni < 8; ni++) {
        int col = h * 64 + ni * 8 + tg * 2;
        int row = q0 + wid * 16 + g;
        float2 o;
        o.x = acc[ni][0]; o.y = acc[ni][1];
        *(float2*)&ctx[(size_t)(b * Sq + row) * DMq + col] = o;
        o.x = acc[ni][2]; o.y = acc[ni][3];
        *(float2*)&ctx[(size_t)(b * Sq + row + 8) * DMq + col] = o;
    }
}

// ---------------------------------------------------------------------------
extern "C" void kernel_launch(void* const* d_in, const int* in_sizes, int n_in,
                              void* d_out, int out_size)
{
    const float* Q    = (const float*)d_in[0];
    const float* K    = (const float*)d_in[1];
    const float* V    = (const float*)d_in[2];
    const float* mask = (const float*)d_in[3];
    const float* Wq   = (const float*)d_in[4];
    const float* bq   = (const float*)d_in[5];
    const float* Wk   = (const float*)d_in[6];
    const float* bk   = (const float*)d_in[7];
    const float* Wv   = (const float*)d_in[8];
    const float* bv   = (const float*)d_in[9];
    const float* Wo   = (const float*)d_in[10];
    const float* bo   = (const float*)d_in[11];

    __nv_bfloat16 *qhi, *qlo, *khi, *klo, *vhi, *vlo;
    float *cp, *pm, *pz, *rm, *ri;
    cudaGetSymbolAddress((void**)&qhi, g_qhi);
    cudaGetSymbolAddress((void**)&qlo, g_qlo);
    cudaGetSymbolAddress((void**)&khi, g_khi);
    cudaGetSymbolAddress((void**)&klo, g_klo);
    cudaGetSymbolAddress((void**)&vhi, g_vhi);
    cudaGetSymbolAddress((void**)&vlo, g_vlo);
    cudaGetSymbolAddress((void**)&cp, g_ctx);
    cudaGetSymbolAddress((void**)&pm, g_pm);
    cudaGetSymbolAddress((void**)&pz, g_pz);
    cudaGetSymbolAddress((void**)&rm, g_rowm);
    cudaGetSymbolAddress((void**)&ri, g_rowinv);

    float* Y   = (float*)d_out;
    float* att = Y + Y_ELEMS;

    cudaFuncSetAttribute(scores_mma_kernel,
                         cudaFuncAttributeMaxDynamicSharedMemorySize, SC_SMEM_BYTES);
    cudaFuncSetAttribute(ctx_mma_kernel,
                         cudaFuncAttributeMaxDynamicSharedMemorySize, CTX_SMEM_BYTES);

    dim3 gproj(DMq / 128, BSq / 128);   // (4, 64)
    gemm_bias128_kernel<<<gproj, 256>>>(Q, Wq, bq, nullptr, qhi, qlo, BSq, DMq, DMq);
    gemm_bias128_kernel<<<gproj, 256>>>(K, Wk, bk, nullptr, khi, klo, BSq, DMq, DMq);
    gemm_bias128_kernel<<<gproj, 256>>>(V, Wv, bv, nullptr, vhi, vlo, BSq, DMq, DMq);

    dim3 gsc(Sq / 128, Sq / 128, Bq * Hq);  // (16, 16, 32)
    scores_mma_kernel<<<gsc, 256, SC_SMEM_BYTES>>>(qhi, qlo, khi, klo, mask, att, pm, pz);

    softmax_reduce_kernel<<<NROWS / 256, 256>>>(pm, pz, rm, ri);

    dim3 gctx(Sq / 128, Bq * Hq);           // (16, 32)
    ctx_mma_kernel<<<gctx, 256, CTX_SMEM_BYTES>>>(att, vhi, vlo, rm, ri, cp);

    gemm_bias128_kernel<<<gproj, 256>>>(cp, Wo, bo, Y, nullptr, nullptr, BSq, DMq, DMq);
}